// round 11
// baseline (speedup 1.0000x reference)
#include <cuda_runtime.h>
#include <cstdint>

namespace {
constexpr int BTOT = 32768;
constexpr int T = 28;
constexpr int D = 28;
constexpr int H = 10;
constexpr int BLK = 128;   // threads per CTA
constexpr int SPB = 64;    // samples per CTA (4 lanes x 2 samples per thread)

__device__ __forceinline__ float sigm(float x) {
    float e = __expf(-x);
    return __fdividef(1.0f, 1.0f + e);
}
__device__ __forceinline__ float tanh_(float x) {
    float e = __expf(2.0f * x);
    return 1.0f - __fdividef(2.0f, e + 1.0f);
}
__device__ __forceinline__ void fma2(uint64_t& d, uint64_t a, uint64_t b) {
    asm("fma.rn.f32x2 %0, %1, %2, %0;" : "+l"(d) : "l"(a), "l"(b));
}
__device__ __forceinline__ void unp2(uint64_t v, float& lo, float& hi) {
    asm("mov.b64 {%0, %1}, %2;" : "=f"(lo), "=f"(hi) : "l"(v));
}

// Gate rows 0..39 = i(0-9), f(10-19), g(20-29), o(30-39).
// Packed accumulator row j = a*2+p (a=unit 0..9): p=0 -> (i_a, f_a), p=1 -> (g_a, o_a).
// f32x2 element c: c=0 -> gate row a+p*20 ; c=1 -> row a+10+p*20.
// Lane l (0..3): p = l&1, unit group a0 = (l>>1)*5 (units a0..a0+4).

__global__ void __launch_bounds__(BLK, 4) lstm_all(
    const float* __restrict__ x,
    const float* __restrict__ w_ih0, const float* __restrict__ w_hh0,
    const float* __restrict__ b_ih0, const float* __restrict__ b_hh0,
    const float* __restrict__ w_ih1, const float* __restrict__ w_hh1,
    const float* __restrict__ b_ih1, const float* __restrict__ b_hh1,
    const float* __restrict__ w_cls, const float* __restrict__ b_cls,
    float* __restrict__ out)
{
    __shared__ __align__(16) float s_wx [20 * D * 2];   // [j][d][c]   1120 f
    __shared__ __align__(16) float s_w0h[20 * H * 2];   // [j][k][c]    400 f
    __shared__ __align__(16) float s_w1i[20 * H * 2];
    __shared__ __align__(16) float s_w1h[20 * H * 2];
    __shared__ __align__(8)  float s_b0p[40];           // [j][c]
    __shared__ __align__(8)  float s_b1p[40];
    __shared__ float s_wc[100];
    __shared__ float s_bc[10];
    __shared__ __align__(16) float s_xd[SPB * 60];      // x dup'd {v,v}; row 60f=240B (15 gran, odd)
    __shared__ __align__(16) float s_h0[SPB * 20];      // h dup'd {h,h}; row 20f=80B (5 gran, odd)
    __shared__ __align__(16) float s_h1[SPB * 20];

    const int tid = threadIdx.x;

    // ---- stage packed weights / biases; zero h buffers ----
    for (int i = tid; i < 20 * D * 2; i += BLK) {
        int c = i & 1, dd = (i >> 1) % D, j = (i >> 1) / D;
        int a = j >> 1, p = j & 1;
        s_wx[i] = w_ih0[(a + p * 20 + c * 10) * D + dd];
    }
    for (int i = tid; i < 20 * H * 2; i += BLK) {
        int c = i & 1, k = (i >> 1) % H, j = (i >> 1) / H;
        int a = j >> 1, p = j & 1;
        int row = a + p * 20 + c * 10;
        s_w0h[i] = w_hh0[row * H + k];
        s_w1i[i] = w_ih1[row * H + k];
        s_w1h[i] = w_hh1[row * H + k];
    }
    for (int i = tid; i < 40; i += BLK) {
        int c = i & 1, j = i >> 1, a = j >> 1, p = j & 1;
        int row = a + p * 20 + c * 10;
        s_b0p[i] = b_ih0[row] + b_hh0[row];
        s_b1p[i] = b_ih1[row] + b_hh1[row];
    }
    for (int i = tid; i < 100; i += BLK) s_wc[i] = w_cls[i];
    if (tid < 10) s_bc[tid] = b_cls[tid];
    for (int i = tid; i < SPB * 20; i += BLK) { s_h0[i] = 0.0f; s_h1[i] = 0.0f; }

    const int l  = tid & 3;
    const int p  = l & 1;
    const int a0 = (l >> 1) * 5;
    const int gq = tid >> 2;          // 0..31
    const int s0 = gq, s1 = gq + 32;  // thread's two samples (CTA-local)

    // unified lo-gate activation: p=0 -> sigm, p=1 -> tanh
    const float scl = p ? 2.0f : -1.0f;
    const float A_  = p ? 1.0f : 0.0f;
    const float B_  = p ? -2.0f : 1.0f;

    const float* wxl  = s_wx  + (a0 * 2 + p) * (D * 2);   // +u*112 floats, +q*4
    const float* w0l  = s_w0h + (a0 * 2 + p) * (H * 2);   // +u*40, +q*4
    const float* w1il = s_w1i + (a0 * 2 + p) * (H * 2);
    const float* w1hl = s_w1h + (a0 * 2 + p) * (H * 2);
    const float* b0l  = s_b0p + (a0 * 2 + p) * 2;         // +u*4
    const float* b1l  = s_b1p + (a0 * 2 + p) * 2;

    float c0[2][5], c1[2][5];
    #pragma unroll
    for (int sm = 0; sm < 2; sm++)
        #pragma unroll
        for (int u = 0; u < 5; u++) { c0[sm][u] = 0.0f; c1[sm][u] = 0.0f; }

    const int s_init = tid / D;
    const int d_init = tid - s_init * D;
    const float* xblk = x + (size_t)blockIdx.x * SPB * (T * D);

    #pragma unroll 1
    for (int t = 0; t < T; t++) {
        __syncthreads();
        {   // coalesced stage of x[64 samples][t][0..27], written duplicated {v,v}
            const float* src = xblk + t * D;
            int e = tid, s = s_init, d = d_init;
            #pragma unroll
            for (int k = 0; k < SPB * D / BLK; k++) {   // 14
                float v = src[e + s * (T * D - D)];
                *(float2*)(s_xd + s * 60 + 2 * d) = make_float2(v, v);
                e += BLK;
                d += (BLK - 4 * D);   // +16
                s += 4;
                if (d >= D) { d -= D; s += 1; }
            }
        }
        __syncthreads();

        uint64_t acc[2][5];
        #pragma unroll
        for (int u = 0; u < 5; u++) {
            acc[0][u] = *(const uint64_t*)(b0l + 4 * u);
            acc[1][u] = acc[0][u];
        }

        // ---------- layer 0: x-projection ----------
        #pragma unroll
        for (int q = 0; q < D / 2; q++) {
            ulonglong2 xv0 = *(const ulonglong2*)(s_xd + s0 * 60 + q * 4);
            ulonglong2 xv1 = *(const ulonglong2*)(s_xd + s1 * 60 + q * 4);
            #pragma unroll
            for (int u = 0; u < 5; u++) {
                ulonglong2 w = *(const ulonglong2*)(wxl + u * (D * 2 * 2) + q * 4);
                fma2(acc[0][u], w.x, xv0.x); fma2(acc[0][u], w.y, xv0.y);
                fma2(acc[1][u], w.x, xv1.x); fma2(acc[1][u], w.y, xv1.y);
            }
        }
        // ---------- layer 0: recurrent ----------
        #pragma unroll
        for (int q = 0; q < H / 2; q++) {
            ulonglong2 hv0 = *(const ulonglong2*)(s_h0 + s0 * 20 + q * 4);
            ulonglong2 hv1 = *(const ulonglong2*)(s_h0 + s1 * 20 + q * 4);
            #pragma unroll
            for (int u = 0; u < 5; u++) {
                ulonglong2 w = *(const ulonglong2*)(w0l + u * (H * 2 * 2) + q * 4);
                fma2(acc[0][u], w.x, hv0.x); fma2(acc[0][u], w.y, hv0.y);
                fma2(acc[1][u], w.x, hv1.x); fma2(acc[1][u], w.y, hv1.y);
            }
        }
        // ---------- layer 0: gates + cell ----------
        __syncwarp();   // all lanes done reading s_h0 before owner overwrites
        #pragma unroll
        for (int sm = 0; sm < 2; sm++) {
            const int s = sm ? s1 : s0;
            #pragma unroll
            for (int u = 0; u < 5; u++) {
                float lo, hi; unp2(acc[sm][u], lo, hi);
                float loA = fmaf(B_, __fdividef(1.0f, 1.0f + __expf(scl * lo)), A_);
                float hiA = sigm(hi);
                float oLoA = __shfl_xor_sync(0xffffffffu, loA, 1);
                float oHiA = __shfl_xor_sync(0xffffffffu, hiA, 1);
                float prod = loA * oLoA;                 // sigm(i)*tanh(g), both roles
                float fv = p ? oHiA : hiA;
                float ov = p ? hiA : oHiA;
                float cn = fmaf(fv, c0[sm][u], prod);
                c0[sm][u] = cn;
                float ht = ov * tanh_(cn);
                if (p == 0)
                    *(float2*)(s_h0 + s * 20 + (a0 + u) * 2) = make_float2(ht, ht);
            }
        }
        __syncwarp();

        // ---------- layer 1 ----------
        #pragma unroll
        for (int u = 0; u < 5; u++) {
            acc[0][u] = *(const uint64_t*)(b1l + 4 * u);
            acc[1][u] = acc[0][u];
        }
        #pragma unroll
        for (int q = 0; q < H / 2; q++) {       // input = new h0
            ulonglong2 hv0 = *(const ulonglong2*)(s_h0 + s0 * 20 + q * 4);
            ulonglong2 hv1 = *(const ulonglong2*)(s_h0 + s1 * 20 + q * 4);
            #pragma unroll
            for (int u = 0; u < 5; u++) {
                ulonglong2 w = *(const ulonglong2*)(w1il + u * (H * 2 * 2) + q * 4);
                fma2(acc[0][u], w.x, hv0.x); fma2(acc[0][u], w.y, hv0.y);
                fma2(acc[1][u], w.x, hv1.x); fma2(acc[1][u], w.y, hv1.y);
            }
        }
        #pragma unroll
        for (int q = 0; q < H / 2; q++) {       // recurrent = old h1
            ulonglong2 hv0 = *(const ulonglong2*)(s_h1 + s0 * 20 + q * 4);
            ulonglong2 hv1 = *(const ulonglong2*)(s_h1 + s1 * 20 + q * 4);
            #pragma unroll
            for (int u = 0; u < 5; u++) {
                ulonglong2 w = *(const ulonglong2*)(w1hl + u * (H * 2 * 2) + q * 4);
                fma2(acc[0][u], w.x, hv0.x); fma2(acc[0][u], w.y, hv0.y);
                fma2(acc[1][u], w.x, hv1.x); fma2(acc[1][u], w.y, hv1.y);
            }
        }
        __syncwarp();
        #pragma unroll
        for (int sm = 0; sm < 2; sm++) {
            const int s = sm ? s1 : s0;
            #pragma unroll
            for (int u = 0; u < 5; u++) {
                float lo, hi; unp2(acc[sm][u], lo, hi);
                float loA = fmaf(B_, __fdividef(1.0f, 1.0f + __expf(scl * lo)), A_);
                float hiA = sigm(hi);
                float oLoA = __shfl_xor_sync(0xffffffffu, loA, 1);
                float oHiA = __shfl_xor_sync(0xffffffffu, hiA, 1);
                float prod = loA * oLoA;
                float fv = p ? oHiA : hiA;
                float ov = p ? hiA : oHiA;
                float cn = fmaf(fv, c1[sm][u], prod);
                c1[sm][u] = cn;
                float ht = ov * tanh_(cn);
                if (p == 0)
                    *(float2*)(s_h1 + s * 20 + (a0 + u) * 2) = make_float2(ht, ht);
            }
        }
        __syncwarp();
    }

    // ---------- classifier: out = h1 @ w_cls^T + b_cls ----------
    #pragma unroll
    for (int r = l; r < 10; r += 4) {
        #pragma unroll
        for (int sm = 0; sm < 2; sm++) {
            const int s = sm ? s1 : s0;
            float acc = s_bc[r];
            #pragma unroll
            for (int k = 0; k < H; k++)
                acc = fmaf(s_wc[r * 10 + k], s_h1[s * 20 + 2 * k], acc);
            out[((size_t)blockIdx.x * SPB + s) * 10 + r] = acc;
        }
    }
}
} // namespace

extern "C" void kernel_launch(void* const* d_in, const int* in_sizes, int n_in,
                              void* d_out, int out_size)
{
    (void)in_sizes; (void)n_in; (void)out_size;
    const float* x     = (const float*)d_in[0];
    const float* w_ih0 = (const float*)d_in[1];
    const float* w_hh0 = (const float*)d_in[2];
    const float* b_ih0 = (const float*)d_in[3];
    const float* b_hh0 = (const float*)d_in[4];
    const float* w_ih1 = (const float*)d_in[5];
    const float* w_hh1 = (const float*)d_in[6];
    const float* b_ih1 = (const float*)d_in[7];
    const float* b_hh1 = (const float*)d_in[8];
    const float* w_cls = (const float*)d_in[9];
    const float* b_cls = (const float*)d_in[10];

    lstm_all<<<BTOT / SPB, BLK>>>(x, w_ih0, w_hh0, b_ih0, b_hh0,
                                  w_ih1, w_hh1, b_ih1, b_hh1,
                                  w_cls, b_cls, (float*)d_out);
}